// round 15
// baseline (speedup 1.0000x reference)
#include <cuda_runtime.h>
#include <math.h>

#define HD 256      // hidden dim
#define BB 2        // batch
#define LL 512      // seq len (L1 == L2)
#define NHEAD 8
#define DHEAD 32

// ---------------- scratch (device globals; no allocation) ----------------
__device__ float g_q [BB*LL*HD];                 // 1 MB
__device__ float g_k [BB*LL*HD];                 // 1 MB
__device__ float g_h1[BB*LL*HD];                 // 1 MB (includes +b1)
__device__ float g_h2[BB*LL*HD];                 // 1 MB
__device__ float g_logits[(size_t)BB*NHEAD*LL*LL]; // 16 MB logits
__device__ float g_alpha[BB*LL];                 // sum_c (w/2) h1[b,i,c]
__device__ float g_beta [BB*LL];                 // sum_c (w/2) h2[b,j,c]

// ---------------- packed fp32x2 helpers (Blackwell) ----------------
typedef unsigned long long u64p;

__device__ __forceinline__ void f2_unpack(u64p p, float& lo, float& hi) {
    asm("mov.b64 {%0, %1}, %2;" : "=f"(lo), "=f"(hi) : "l"(p));
}
__device__ __forceinline__ u64p f2_pack(float lo, float hi) {
    u64p r; asm("mov.b64 %0, {%1, %2};" : "=l"(r) : "f"(lo), "f"(hi)); return r;
}
__device__ __forceinline__ u64p f2_fma(u64p a, u64p b, u64p c) {
    u64p d; asm("fma.rn.f32x2 %0, %1, %2, %3;" : "=l"(d) : "l"(a), "l"(b), "l"(c)); return d;
}
__device__ __forceinline__ u64p f2_add(u64p a, u64p b) {
    u64p d; asm("add.rn.f32x2 %0, %1, %2;" : "=l"(d) : "l"(a), "l"(b)); return d;
}
__device__ __forceinline__ u64p f2_abs(u64p x) {
    float lo, hi; f2_unpack(x, lo, hi);
    lo = fabsf(lo); hi = fabsf(hi);
    return f2_pack(lo, hi);
}

#define SMS 36   // smem row stride (floats): granule stride 9 (odd) -> conflict-free

// =========================================================================
// K1: projections (K-packed).  job z: 0=q 1=k 2=h1(+b1) 3=h2
// 64x64 tile, 256 threads, 4i x 4j/thread; f32x2 packed along K.
// grid (4, 16, 4) = 256 blocks.
// =========================================================================
__global__ __launch_bounds__(256) void proj_kernel(
    const float* __restrict__ e1, const float* __restrict__ e2,
    const float* __restrict__ ipw, const float* __restrict__ ipb,
    const float* __restrict__ W1,  const float* __restrict__ b1)
{
    const int job = blockIdx.z;
    const float* A; const float* W; const float* bias; int ldw; float* C;
    if (job == 0)      { A = e1; W = ipw;           bias = ipb;      ldw = HD;   C = g_q;  }
    else if (job == 1) { A = e2; W = ipw + HD*HD;   bias = ipb + HD; ldw = HD;   C = g_k;  }
    else if (job == 2) { A = e1; W = W1;            bias = b1;       ldw = 2*HD; C = g_h1; }
    else               { A = e2; W = W1 + HD;       bias = nullptr;  ldw = 2*HD; C = g_h2; }

    const int i0 = blockIdx.y * 64;
    const int j0 = blockIdx.x * 64;

    __shared__ __align__(16) float sA[64][SMS];   // [i-row][k] 32 k used
    __shared__ __align__(16) float sW[64][SMS];   // [j-row][k]

    const int tid = threadIdx.x;
    const int ty = tid >> 4;       // rows i0 + ty*4 + u
    const int tx = tid & 15;       // cols j0 + tx + 16*v

    u64p acc[4][4] = {};   // [u][v], packed over k-parity

    for (int k0 = 0; k0 < HD; k0 += 32) {
        float4 va[2], vw[2];
        int row_[2], kq[2];
#pragma unroll
        for (int r = 0; r < 2; r++) {
            int pidx = tid + r * 256;
            row_[r] = pidx >> 3; kq[r] = (pidx & 7) << 2;
            va[r] = *(const float4*)&A[(size_t)(i0 + row_[r]) * HD  + k0 + kq[r]];
            vw[r] = *(const float4*)&W[(size_t)(j0 + row_[r]) * ldw + k0 + kq[r]];
        }
        __syncthreads();
#pragma unroll
        for (int r = 0; r < 2; r++) {
            *(float4*)&sA[row_[r]][kq[r]] = va[r];
            *(float4*)&sW[row_[r]][kq[r]] = vw[r];
        }
        __syncthreads();

#pragma unroll
        for (int kk4 = 0; kk4 < 32; kk4 += 4) {
            ulonglong2 a[4], w[4];
#pragma unroll
            for (int u = 0; u < 4; u++) a[u] = *(const ulonglong2*)&sA[ty*4 + u][kk4];
#pragma unroll
            for (int v = 0; v < 4; v++) w[v] = *(const ulonglong2*)&sW[tx + 16*v][kk4];
#pragma unroll
            for (int u = 0; u < 4; u++)
#pragma unroll
                for (int v = 0; v < 4; v++) {
                    acc[u][v] = f2_fma(a[u].x, w[v].x, acc[u][v]);
                    acc[u][v] = f2_fma(a[u].y, w[v].y, acc[u][v]);
                }
        }
        __syncthreads();
    }

    float bv[4] = {0.f, 0.f, 0.f, 0.f};
    if (bias) {
#pragma unroll
        for (int v = 0; v < 4; v++) bv[v] = bias[j0 + tx + 16*v];
    }
#pragma unroll
    for (int u = 0; u < 4; u++) {
        const size_t rowoff = (size_t)(i0 + ty*4 + u) * HD + j0 + tx;
#pragma unroll
        for (int v = 0; v < 4; v++) {
            float lo, hi;
            f2_unpack(acc[u][v], lo, hi);
            C[rowoff + 16*v] = lo + hi + bv[v];
        }
    }
}

// =========================================================================
// K1.5: alpha/beta.  alpha[r] = sum_c (w2[c]/2) h1[r,c]; beta likewise h2.
// grid 128 blocks x 256 threads; warp w handles row blockIdx*8+w.
// =========================================================================
__global__ __launch_bounds__(256) void alphabeta_kernel(const float* __restrict__ W2)
{
    const int row  = blockIdx.x * 8 + (threadIdx.x >> 5);   // 0..1023
    const int lane = threadIdx.x & 31;

    const float4 w0 = *(const float4*)&W2[lane * 8];
    const float4 w1 = *(const float4*)&W2[lane * 8 + 4];

    const float4 a0 = *(const float4*)&g_h1[(size_t)row * HD + lane * 8];
    const float4 a1 = *(const float4*)&g_h1[(size_t)row * HD + lane * 8 + 4];
    const float4 b0 = *(const float4*)&g_h2[(size_t)row * HD + lane * 8];
    const float4 b1 = *(const float4*)&g_h2[(size_t)row * HD + lane * 8 + 4];

    float a = a0.x*w0.x + a0.y*w0.y + a0.z*w0.z + a0.w*w0.w
            + a1.x*w1.x + a1.y*w1.y + a1.z*w1.z + a1.w*w1.w;
    float b = b0.x*w0.x + b0.y*w0.y + b0.z*w0.z + b0.w*w0.w
            + b1.x*w1.x + b1.y*w1.y + b1.z*w1.z + b1.w*w1.w;

#pragma unroll
    for (int o = 16; o; o >>= 1) {
        a += __shfl_xor_sync(0xffffffffu, a, o);
        b += __shfl_xor_sync(0xffffffffu, b, o);
    }
    if (lane == 0) {
        g_alpha[row] = 0.5f * a;
        g_beta [row] = 0.5f * b;
    }
}

// =========================================================================
// K2 (FUSED): match-final tiles (z<2, HEAVY, launched first) + logits (z>=2).
// Both: 64x64 tile, 128 threads, 8i x 4j/thread, f32x2 packed along K.
// grid (8, 8, 2+16) = 1152 blocks of 4 warps.
//
// match: out[b,i,j] = sigmoid(alpha_i + beta_j + sum_c (w2[c]/2)|h1+h2| + b2)
//        (z = b, K = 256 in 8 chunks)
// logits[b,h,i,j] = (1/sqrt(32)) * sum_d q*k   (z-2 = b*8+h, K = 32)
// =========================================================================
__global__ __launch_bounds__(128) void mid_kernel(
    const float* __restrict__ W2, const float* __restrict__ b2,
    float* __restrict__ out)
{
    const int z  = blockIdx.z;
    const int i0 = blockIdx.y * 64;
    const int j0 = blockIdx.x * 64;

    __shared__ __align__(16) float sA[64][SMS];   // [i-row][k], 32 k used
    __shared__ __align__(16) float sB[64][SMS];   // [j-row][k]
    __shared__ __align__(16) float sw[HD];        // w2/2 (match only)

    const int tid = threadIdx.x;
    const int ty = tid >> 4;       // 0..7  -> rows i0 + ty*8 + u
    const int tx = tid & 15;       // cols j0 + tx + 16*v

    u64p acc[8][4] = {};   // [u][v], k-packed

    if (z < 2) {
        // ---------------- match tile: K = 256, 8 chunks, direct output ----
        const int b = z;
        const float* Ag = g_h1 + (size_t)b * LL * HD;
        const float* Bg = g_h2 + (size_t)b * LL * HD;

        sw[tid]       = 0.5f * W2[tid];
        sw[tid + 128] = 0.5f * W2[tid + 128];

        for (int kc = 0; kc < HD; kc += 32) {
            float4 va[4], vb[4];
            int rr[4], kq[4];
#pragma unroll
            for (int r = 0; r < 4; r++) {
                int pidx = tid + r * 128;
                rr[r] = pidx >> 3; kq[r] = (pidx & 7) << 2;
                va[r] = *(const float4*)&Ag[(size_t)(i0 + rr[r]) * HD + kc + kq[r]];
                vb[r] = *(const float4*)&Bg[(size_t)(j0 + rr[r]) * HD + kc + kq[r]];
            }
            __syncthreads();
#pragma unroll
            for (int r = 0; r < 4; r++) {
                *(float4*)&sA[rr[r]][kq[r]] = va[r];
                *(float4*)&sB[rr[r]][kq[r]] = vb[r];
            }
            __syncthreads();

#pragma unroll
            for (int k4 = 0; k4 < 32; k4 += 4) {
                const u64p w01 = *(const u64p*)&sw[kc + k4];
                const u64p w23 = *(const u64p*)&sw[kc + k4 + 2];
                ulonglong2 bq[4];
#pragma unroll
                for (int v = 0; v < 4; v++)
                    bq[v] = *(const ulonglong2*)&sB[tx + 16*v][k4];
#pragma unroll
                for (int u = 0; u < 8; u++) {
                    const ulonglong2 aq = *(const ulonglong2*)&sA[ty*8 + u][k4];
#pragma unroll
                    for (int v = 0; v < 4; v++) {
                        acc[u][v] = f2_fma(f2_abs(f2_add(aq.x, bq[v].x)), w01, acc[u][v]);
                        acc[u][v] = f2_fma(f2_abs(f2_add(aq.y, bq[v].y)), w23, acc[u][v]);
                    }
                }
            }
        }

        const float bias2 = b2[0];
        float al[8], be[4];
#pragma unroll
        for (int u = 0; u < 8; u++) al[u] = g_alpha[b*LL + i0 + ty*8 + u];
#pragma unroll
        for (int v = 0; v < 4; v++) be[v] = g_beta[b*LL + j0 + tx + 16*v];

        float* O = out + (size_t)BB * LL * LL + (size_t)b * LL * LL;
#pragma unroll
        for (int u = 0; u < 8; u++) {
            const size_t ro = (size_t)(i0 + ty*8 + u) * LL + j0 + tx;
#pragma unroll
            for (int v = 0; v < 4; v++) {
                float lo, hi;
                f2_unpack(acc[u][v], lo, hi);
                float x = al[u] + be[v] + lo + hi + bias2;
                O[ro + 16*v] = 1.0f / (1.0f + __expf(-x));
            }
        }
    } else {
        // ---------------- logits tile: K = 32, single chunk ----------------
        const int zz = z - 2;
        const int b = zz >> 3, h = zz & 7;
        const float* Ag = g_q + (size_t)b * LL * HD + h * DHEAD;
        const float* Bg = g_k + (size_t)b * LL * HD + h * DHEAD;

        {
            float4 va[4], vb[4];
            int rr[4], kq[4];
#pragma unroll
            for (int r = 0; r < 4; r++) {
                int pidx = tid + r * 128;
                rr[r] = pidx >> 3; kq[r] = (pidx & 7) << 2;
                va[r] = *(const float4*)&Ag[(size_t)(i0 + rr[r]) * HD + kq[r]];
                vb[r] = *(const float4*)&Bg[(size_t)(j0 + rr[r]) * HD + kq[r]];
            }
#pragma unroll
            for (int r = 0; r < 4; r++) {
                *(float4*)&sA[rr[r]][kq[r]] = va[r];
                *(float4*)&sB[rr[r]][kq[r]] = vb[r];
            }
        }
        __syncthreads();

#pragma unroll
        for (int k4 = 0; k4 < 32; k4 += 4) {
            ulonglong2 bq[4];
#pragma unroll
            for (int v = 0; v < 4; v++)
                bq[v] = *(const ulonglong2*)&sB[tx + 16*v][k4];
#pragma unroll
            for (int u = 0; u < 8; u++) {
                const ulonglong2 aq = *(const ulonglong2*)&sA[ty*8 + u][k4];
#pragma unroll
                for (int v = 0; v < 4; v++) {
                    acc[u][v] = f2_fma(aq.x, bq[v].x, acc[u][v]);
                    acc[u][v] = f2_fma(aq.y, bq[v].y, acc[u][v]);
                }
            }
        }
        const float scale = 0.1767766952966369f; // 1/sqrt(32)
        float* C = g_logits + (size_t)zz * LL * LL;
#pragma unroll
        for (int u = 0; u < 8; u++) {
            const size_t ro = (size_t)(i0 + ty*8 + u) * LL + j0 + tx;
#pragma unroll
            for (int v = 0; v < 4; v++) {
                float lo, hi;
                f2_unpack(acc[u][v], lo, hi);
                C[ro + 16*v] = (lo + hi) * scale;
            }
        }
    }
}

// =========================================================================
// K3: softmax + head-mean.  One block per (b,i); warp h owns head h's row.
// =========================================================================
__global__ __launch_bounds__(256) void softmax_mean_kernel(float* __restrict__ out)
{
    const int b = blockIdx.x >> 9;
    const int i = blockIdx.x & 511;
    const int wid  = threadIdx.x >> 5;
    const int lane = threadIdx.x & 31;
    const int t = threadIdx.x;

    __shared__ float p[8][512];

    const float* row = g_logits + ((size_t)(b*8 + wid) * LL + i) * LL;

    float v[16];
    float mx = -1e30f;
#pragma unroll
    for (int r = 0; r < 16; r++) {
        v[r] = row[lane + 32*r];
        mx = fmaxf(mx, v[r]);
    }
#pragma unroll
    for (int o = 16; o; o >>= 1) mx = fmaxf(mx, __shfl_xor_sync(0xffffffffu, mx, o));

    float s = 0.0f;
#pragma unroll
    for (int r = 0; r < 16; r++) { v[r] = __expf(v[r] - mx); s += v[r]; }
#pragma unroll
    for (int o = 16; o; o >>= 1) s += __shfl_xor_sync(0xffffffffu, s, o);
    const float inv = 1.0f / s;

#pragma unroll
    for (int r = 0; r < 16; r++) p[wid][lane + 32*r] = v[r] * inv;

    __syncthreads();

    const size_t o = ((size_t)b * LL + i) * LL;
#pragma unroll
    for (int jj = 0; jj < 2; jj++) {
        int j = t + jj * 256;
        float a = 0.0f;
#pragma unroll
        for (int h = 0; h < 8; h++) a += p[h][j];
        out[o + j] = a * 0.125f;
    }
}

// =========================================================================
extern "C" void kernel_launch(void* const* d_in, const int* in_sizes, int n_in,
                              void* d_out, int out_size)
{
    const float* e1  = (const float*)d_in[0];  // (B,L1,H)
    const float* e2  = (const float*)d_in[1];  // (B,L2,H)
    const float* ipw = (const float*)d_in[2];  // (3H,H)
    const float* ipb = (const float*)d_in[3];  // (3H,)
    const float* W1  = (const float*)d_in[4];  // (H,2H)
    const float* b1  = (const float*)d_in[5];  // (H,)
    const float* W2  = (const float*)d_in[6];  // (1,H)
    const float* b2  = (const float*)d_in[7];  // (1,)
    float* out = (float*)d_out;                // [attn (B,L1,L2)] ++ [match (B,L1,L2)]

    proj_kernel <<<dim3(HD/64, (BB*LL)/64, 4), 256>>>(e1, e2, ipw, ipb, W1, b1);
    alphabeta_kernel<<<BB*LL/8, 256>>>(W2);
    mid_kernel  <<<dim3(LL/64, LL/64, 2 + 16), 128>>>(W2, b2, out);
    softmax_mean_kernel<<<BB*LL, 256>>>(out);
}

// round 16
// speedup vs baseline: 1.1735x; 1.1735x over previous
#include <cuda_runtime.h>
#include <math.h>

#define HD 256      // hidden dim
#define BB 2        // batch
#define LL 512      // seq len (L1 == L2)
#define NHEAD 8
#define DHEAD 32
#define NSPLIT 4    // match channel splits (64 channels each)

// ---------------- scratch (device globals; no allocation) ----------------
__device__ float g_q [BB*LL*HD];                 // 1 MB
__device__ float g_k [BB*LL*HD];                 // 1 MB
__device__ float g_h1[BB*LL*HD];                 // 1 MB (includes +b1)
__device__ float g_h2[BB*LL*HD];                 // 1 MB
__device__ float g_logits[(size_t)BB*NHEAD*LL*LL]; // 16 MB logits
__device__ float g_part[(size_t)NSPLIT*BB*LL*LL];  // 8 MB match partials
__device__ float g_alpha[BB*LL];                 // sum_c (w/2) h1[b,i,c]
__device__ float g_beta [BB*LL];                 // sum_c (w/2) h2[b,j,c]

// ---------------- packed fp32x2 helpers (Blackwell) ----------------
typedef unsigned long long u64p;

__device__ __forceinline__ u64p f2_pack(float lo, float hi) {
    u64p r; asm("mov.b64 %0, {%1, %2};" : "=l"(r) : "f"(lo), "f"(hi)); return r;
}
__device__ __forceinline__ void f2_unpack(u64p p, float& lo, float& hi) {
    asm("mov.b64 {%0, %1}, %2;" : "=f"(lo), "=f"(hi) : "l"(p));
}
__device__ __forceinline__ u64p f2_fma(u64p a, u64p b, u64p c) {
    u64p d; asm("fma.rn.f32x2 %0, %1, %2, %3;" : "=l"(d) : "l"(a), "l"(b), "l"(c)); return d;
}
__device__ __forceinline__ u64p f2_add(u64p a, u64p b) {
    u64p d; asm("add.rn.f32x2 %0, %1, %2;" : "=l"(d) : "l"(a), "l"(b)); return d;
}
__device__ __forceinline__ u64p f2_abs(u64p x) {
    float lo, hi; f2_unpack(x, lo, hi);
    lo = fabsf(lo); hi = fabsf(hi);
    return f2_pack(lo, hi);
}

#define SMS 36   // smem row stride (floats): granule stride 9 (odd) -> conflict-free

// =========================================================================
// K1: projections (K-packed).  job z: 0=q 1=k 2=h1(+b1) 3=h2
// 64x64 tile, 256 threads, 4i x 4j/thread; f32x2 packed along K.
// grid (4, 16, 4) = 256 blocks.
// =========================================================================
__global__ __launch_bounds__(256) void proj_kernel(
    const float* __restrict__ e1, const float* __restrict__ e2,
    const float* __restrict__ ipw, const float* __restrict__ ipb,
    const float* __restrict__ W1,  const float* __restrict__ b1)
{
    const int job = blockIdx.z;
    const float* A; const float* W; const float* bias; int ldw; float* C;
    if (job == 0)      { A = e1; W = ipw;           bias = ipb;      ldw = HD;   C = g_q;  }
    else if (job == 1) { A = e2; W = ipw + HD*HD;   bias = ipb + HD; ldw = HD;   C = g_k;  }
    else if (job == 2) { A = e1; W = W1;            bias = b1;       ldw = 2*HD; C = g_h1; }
    else               { A = e2; W = W1 + HD;       bias = nullptr;  ldw = 2*HD; C = g_h2; }

    const int i0 = blockIdx.y * 64;
    const int j0 = blockIdx.x * 64;

    __shared__ __align__(16) float sA[64][SMS];   // [i-row][k] 32 k used
    __shared__ __align__(16) float sW[64][SMS];   // [j-row][k]

    const int tid = threadIdx.x;
    const int ty = tid >> 4;       // rows i0 + ty*4 + u
    const int tx = tid & 15;       // cols j0 + tx + 16*v

    u64p acc[4][4] = {};   // [u][v], packed over k-parity

    for (int k0 = 0; k0 < HD; k0 += 32) {
        float4 va[2], vw[2];
        int row_[2], kq[2];
#pragma unroll
        for (int r = 0; r < 2; r++) {
            int pidx = tid + r * 256;
            row_[r] = pidx >> 3; kq[r] = (pidx & 7) << 2;
            va[r] = *(const float4*)&A[(size_t)(i0 + row_[r]) * HD  + k0 + kq[r]];
            vw[r] = *(const float4*)&W[(size_t)(j0 + row_[r]) * ldw + k0 + kq[r]];
        }
        __syncthreads();
#pragma unroll
        for (int r = 0; r < 2; r++) {
            *(float4*)&sA[row_[r]][kq[r]] = va[r];
            *(float4*)&sW[row_[r]][kq[r]] = vw[r];
        }
        __syncthreads();

#pragma unroll
        for (int kk4 = 0; kk4 < 32; kk4 += 4) {
            ulonglong2 a[4], w[4];
#pragma unroll
            for (int u = 0; u < 4; u++) a[u] = *(const ulonglong2*)&sA[ty*4 + u][kk4];
#pragma unroll
            for (int v = 0; v < 4; v++) w[v] = *(const ulonglong2*)&sW[tx + 16*v][kk4];
#pragma unroll
            for (int u = 0; u < 4; u++)
#pragma unroll
                for (int v = 0; v < 4; v++) {
                    acc[u][v] = f2_fma(a[u].x, w[v].x, acc[u][v]);
                    acc[u][v] = f2_fma(a[u].y, w[v].y, acc[u][v]);
                }
        }
        __syncthreads();
    }

    float bv[4] = {0.f, 0.f, 0.f, 0.f};
    if (bias) {
#pragma unroll
        for (int v = 0; v < 4; v++) bv[v] = bias[j0 + tx + 16*v];
    }
#pragma unroll
    for (int u = 0; u < 4; u++) {
        const size_t rowoff = (size_t)(i0 + ty*4 + u) * HD + j0 + tx;
#pragma unroll
        for (int v = 0; v < 4; v++) {
            float lo, hi;
            f2_unpack(acc[u][v], lo, hi);
            C[rowoff + 16*v] = lo + hi + bv[v];
        }
    }
}

// =========================================================================
// K2 (FUSED): match partial tiles (z<8, 2-chunk, launched FIRST) +
//             logits tiles (z>=8, 1-chunk backfill).
// Both: 64x64 tile, 128 threads, 8i x 4j/thread, f32x2 packed along K.
// grid (8, 8, NSPLIT*BB + 16) = (8,8,24) = 1536 blocks of 4 warps.
//
// P[(s*2+b)...]   = sum_{c in split s} (w2[c]/2)*|h1+h2|  (z = s*2+b, K=64)
// logits[b,h,i,j] = (1/sqrt(32)) * sum_d q*k              (z-8 = b*8+h, K=32)
// =========================================================================
__global__ __launch_bounds__(128) void mid_kernel(
    const float* __restrict__ W2, float* __restrict__ P)
{
    const int z  = blockIdx.z;
    const int i0 = blockIdx.y * 64;
    const int j0 = blockIdx.x * 64;

    __shared__ __align__(16) float sA[64][SMS];   // [i-row][k], 32 k used
    __shared__ __align__(16) float sB[64][SMS];   // [j-row][k]
    __shared__ __align__(16) float sw[64];        // w2/2 (match only)

    const int tid = threadIdx.x;
    const int ty = tid >> 4;       // 0..7  -> rows i0 + ty*8 + u
    const int tx = tid & 15;       // cols j0 + tx + 16*v

    u64p acc[8][4] = {};   // [u][v], k-packed

    if (z < NSPLIT*BB) {
        // ---------------- match tile: K = 64, 2 chunks --------------------
        const int b  = z & 1;
        const int s  = z >> 1;
        const int c0 = s * 64;
        const float* Ag = g_h1 + (size_t)b * LL * HD + c0;
        const float* Bg = g_h2 + (size_t)b * LL * HD + c0;

        if (tid < 64) sw[tid] = 0.5f * W2[c0 + tid];

        for (int kc = 0; kc < 64; kc += 32) {
            float4 va[4], vb[4];
            int rr[4], kq[4];
#pragma unroll
            for (int r = 0; r < 4; r++) {
                int pidx = tid + r * 128;
                rr[r] = pidx >> 3; kq[r] = (pidx & 7) << 2;
                va[r] = *(const float4*)&Ag[(size_t)(i0 + rr[r]) * HD + kc + kq[r]];
                vb[r] = *(const float4*)&Bg[(size_t)(j0 + rr[r]) * HD + kc + kq[r]];
            }
            __syncthreads();
#pragma unroll
            for (int r = 0; r < 4; r++) {
                *(float4*)&sA[rr[r]][kq[r]] = va[r];
                *(float4*)&sB[rr[r]][kq[r]] = vb[r];
            }
            __syncthreads();

#pragma unroll
            for (int k4 = 0; k4 < 32; k4 += 4) {
                const u64p w01 = *(const u64p*)&sw[kc + k4];
                const u64p w23 = *(const u64p*)&sw[kc + k4 + 2];
                ulonglong2 bq[4];
#pragma unroll
                for (int v = 0; v < 4; v++)
                    bq[v] = *(const ulonglong2*)&sB[tx + 16*v][k4];
#pragma unroll
                for (int u = 0; u < 8; u++) {
                    const ulonglong2 aq = *(const ulonglong2*)&sA[ty*8 + u][k4];
#pragma unroll
                    for (int v = 0; v < 4; v++) {
                        acc[u][v] = f2_fma(f2_abs(f2_add(aq.x, bq[v].x)), w01, acc[u][v]);
                        acc[u][v] = f2_fma(f2_abs(f2_add(aq.y, bq[v].y)), w23, acc[u][v]);
                    }
                }
            }
        }
        float* Pd = P + (size_t)z * LL * LL;
#pragma unroll
        for (int u = 0; u < 8; u++) {
            const size_t ro = (size_t)(i0 + ty*8 + u) * LL + j0 + tx;
#pragma unroll
            for (int v = 0; v < 4; v++) {
                float lo, hi;
                f2_unpack(acc[u][v], lo, hi);
                Pd[ro + 16*v] = lo + hi;
            }
        }
    } else {
        // ---------------- logits tile: K = 32, single chunk ----------------
        const int zz = z - NSPLIT*BB;
        const int b = zz >> 3, h = zz & 7;
        const float* Ag = g_q + (size_t)b * LL * HD + h * DHEAD;
        const float* Bg = g_k + (size_t)b * LL * HD + h * DHEAD;

        {
            float4 va[4], vb[4];
            int rr[4], kq[4];
#pragma unroll
            for (int r = 0; r < 4; r++) {
                int pidx = tid + r * 128;
                rr[r] = pidx >> 3; kq[r] = (pidx & 7) << 2;
                va[r] = *(const float4*)&Ag[(size_t)(i0 + rr[r]) * HD + kq[r]];
                vb[r] = *(const float4*)&Bg[(size_t)(j0 + rr[r]) * HD + kq[r]];
            }
#pragma unroll
            for (int r = 0; r < 4; r++) {
                *(float4*)&sA[rr[r]][kq[r]] = va[r];
                *(float4*)&sB[rr[r]][kq[r]] = vb[r];
            }
        }
        __syncthreads();

#pragma unroll
        for (int k4 = 0; k4 < 32; k4 += 4) {
            ulonglong2 bq[4];
#pragma unroll
            for (int v = 0; v < 4; v++)
                bq[v] = *(const ulonglong2*)&sB[tx + 16*v][k4];
#pragma unroll
            for (int u = 0; u < 8; u++) {
                const ulonglong2 aq = *(const ulonglong2*)&sA[ty*8 + u][k4];
#pragma unroll
                for (int v = 0; v < 4; v++) {
                    acc[u][v] = f2_fma(aq.x, bq[v].x, acc[u][v]);
                    acc[u][v] = f2_fma(aq.y, bq[v].y, acc[u][v]);
                }
            }
        }
        const float scale = 0.1767766952966369f; // 1/sqrt(32)
        float* C = g_logits + (size_t)zz * LL * LL;
#pragma unroll
        for (int u = 0; u < 8; u++) {
            const size_t ro = (size_t)(i0 + ty*8 + u) * LL + j0 + tx;
#pragma unroll
            for (int v = 0; v < 4; v++) {
                float lo, hi;
                f2_unpack(acc[u][v], lo, hi);
                C[ro + 16*v] = (lo + hi) * scale;
            }
        }
    }
}

// =========================================================================
// K3: softmax + head-mean + alpha/beta (R13 verbatim).
// =========================================================================
__global__ __launch_bounds__(256) void softmax_mean_kernel(
    const float* __restrict__ W2, float* __restrict__ out)
{
    const int b = blockIdx.x >> 9;
    const int i = blockIdx.x & 511;
    const int wid  = threadIdx.x >> 5;
    const int lane = threadIdx.x & 31;
    const int t = threadIdx.x;

    __shared__ float p[8][512];
    __shared__ float reda[8], redb[8];

    const float* row = g_logits + ((size_t)(b*8 + wid) * LL + i) * LL;

    float v[16];
    float mx = -1e30f;
#pragma unroll
    for (int r = 0; r < 16; r++) {
        v[r] = row[lane + 32*r];
        mx = fmaxf(mx, v[r]);
    }
#pragma unroll
    for (int o = 16; o; o >>= 1) mx = fmaxf(mx, __shfl_xor_sync(0xffffffffu, mx, o));

    float s = 0.0f;
#pragma unroll
    for (int r = 0; r < 16; r++) { v[r] = __expf(v[r] - mx); s += v[r]; }
#pragma unroll
    for (int o = 16; o; o >>= 1) s += __shfl_xor_sync(0xffffffffu, s, o);
    const float inv = 1.0f / s;

#pragma unroll
    for (int r = 0; r < 16; r++) p[wid][lane + 32*r] = v[r] * inv;

    {
        const float wh = 0.5f * W2[t];
        float pa = g_h1[((size_t)b*LL + i)*HD + t] * wh;
        float pb = g_h2[((size_t)b*LL + i)*HD + t] * wh;
#pragma unroll
        for (int o = 16; o; o >>= 1) {
            pa += __shfl_xor_sync(0xffffffffu, pa, o);
            pb += __shfl_xor_sync(0xffffffffu, pb, o);
        }
        if (lane == 0) { reda[wid] = pa; redb[wid] = pb; }
    }

    __syncthreads();

    const size_t o = ((size_t)b * LL + i) * LL;
#pragma unroll
    for (int jj = 0; jj < 2; jj++) {
        int j = t + jj * 256;
        float a = 0.0f;
#pragma unroll
        for (int h = 0; h < 8; h++) a += p[h][j];
        out[o + j] = a * 0.125f;
    }

    if (t < 16) {
        float va = (t < 8) ? reda[t] : redb[t - 8];
#pragma unroll
        for (int oo = 4; oo; oo >>= 1) va += __shfl_xor_sync(0xffffffffu, va, oo);
        if (t == 0) g_alpha[b*LL + i] = va;
        if (t == 8) g_beta [b*LL + i] = va;
    }
}

// =========================================================================
// K5: combine: out = sigmoid(alpha_i + beta_j + sum_s P_s + b2)
// P plane index = s*2 + b.
// =========================================================================
__global__ __launch_bounds__(256) void combine_kernel(
    const float* __restrict__ P, const float* __restrict__ b2,
    float* __restrict__ out)
{
    const size_t n  = (size_t)LL * LL;
    const size_t nn = (size_t)BB * LL * LL;
    const size_t idx = ((size_t)blockIdx.x * 256 + threadIdx.x) * 4;
    if (idx >= nn) return;

    const int b = (int)(idx >> 18);
    const int rem = (int)(idx & 262143);
    const int i = rem >> 9;
    const int j = rem & 511;

    float base = g_alpha[b*LL + i] + b2[0];
    float4 bt = *(const float4*)&g_beta[b*LL + j];

    float4 acc = make_float4(base + bt.x, base + bt.y, base + bt.z, base + bt.w);
    const size_t pix = (size_t)rem;
#pragma unroll
    for (int s = 0; s < NSPLIT; s++) {
        float4 ps = *(const float4*)&P[((size_t)(s*2 + b)) * n + pix];
        acc.x += ps.x; acc.y += ps.y; acc.z += ps.z; acc.w += ps.w;
    }
    float4 o;
    o.x = 1.0f / (1.0f + __expf(-acc.x));
    o.y = 1.0f / (1.0f + __expf(-acc.y));
    o.z = 1.0f / (1.0f + __expf(-acc.z));
    o.w = 1.0f / (1.0f + __expf(-acc.w));
    *(float4*)&out[nn + idx] = o;
}

// =========================================================================
extern "C" void kernel_launch(void* const* d_in, const int* in_sizes, int n_in,
                              void* d_out, int out_size)
{
    const float* e1  = (const float*)d_in[0];  // (B,L1,H)
    const float* e2  = (const float*)d_in[1];  // (B,L2,H)
    const float* ipw = (const float*)d_in[2];  // (3H,H)
    const float* ipb = (const float*)d_in[3];  // (3H,)
    const float* W1  = (const float*)d_in[4];  // (H,2H)
    const float* b1  = (const float*)d_in[5];  // (H,)
    const float* W2  = (const float*)d_in[6];  // (1,H)
    const float* b2  = (const float*)d_in[7];  // (1,)
    float* out = (float*)d_out;                // [attn (B,L1,L2)] ++ [match (B,L1,L2)]

    float* P;
    cudaGetSymbolAddress((void**)&P, g_part);

    proj_kernel <<<dim3(HD/64, (BB*LL)/64, 4), 256>>>(e1, e2, ipw, ipb, W1, b1);
    mid_kernel  <<<dim3(LL/64, LL/64, NSPLIT*BB + 16), 128>>>(W2, P);
    softmax_mean_kernel<<<BB*LL, 256>>>(W2, out);
    combine_kernel<<<(unsigned)((BB*LL*LL/4 + 255)/256), 256>>>(P, b2, out);
}